// round 13
// baseline (speedup 1.0000x reference)
#include <cuda_runtime.h>
#include <cuda.h>
#include <cuda_bf16.h>
#include <cuda_fp8.h>
#include <cstdint>

#define MTOT 32768
#define CIN  1024
#define COUT 1024
#define WDIM 512

// ---- GEMM tiling: 128 x 512 output tile, A pinned in smem, B streamed ----
#define GBM 128
#define GBNT 512                     // tile N width
#define GBNQ 128                     // N-quarter (one MMA N)
#define NQ 4                         // quarters per tile
#define GBK 128                      // 128 e4m3 = 128B = one SW128 atom row
#define GNKT (CIN / GBK)             // 8 K-planes
#define BSTAGES 4
#define A_PIN (GNKT * GBM * 128)     // 131072 B (8 planes x 16KB)
#define B_STAGE (GBNQ * 128)         // 16384 B
#define DYN_SMEM (1024 + A_PIN + BSTAGES * B_STAGE)   // 197632

// idesc kind::f8f6f4: dtype=F32(1<<4), E4M3, N=128(16<<17), M=128(8<<24)
#define IDESC_F8 0x08200010u

#if defined(__CUDA_ARCH_FEAT_SM103_ALL) || defined(__CUDA_ARCH_FEAT_SM100_ALL)
#define USE_TCGEN05 1
#elif defined(__CUDA_ARCH_SPECIFIC__) && (__CUDA_ARCH_SPECIFIC__ >= 1000)
#define USE_TCGEN05 1
#elif defined(__CUDA_ARCH_FAMILY_SPECIFIC__) && (__CUDA_ARCH_FAMILY_SPECIFIC__ >= 1000)
#define USE_TCGEN05 1
#else
#define USE_TCGEN05 0
#endif

// Scratch (device globals — no allocation allowed)
// K-BLOCKED fp8 layouts: xb[(kt*MTOT + m)*128 + k%128], wb[(kt*COUT + o)*128 + k%128]
__device__ __align__(1024) uint8_t g_xb[(size_t)MTOT * CIN];   // 32 MB e4m3 (L2-resident)
__device__ __align__(1024) uint8_t g_wb[(size_t)COUT * CIN];   // 1 MB e4m3
__device__ __align__(16) float g_styles[8 * CIN];
__device__ __align__(16) float g_dcoefs[8 * COUT];

// ---------------------------------------------------------------- helpers
__device__ __forceinline__ uint32_t smem_u32(const void* p) {
    uint32_t a;
    asm("{ .reg .u64 t; cvta.to.shared.u64 t, %1; cvt.u32.u64 %0, t; }" : "=r"(a) : "l"(p));
    return a;
}
__device__ __forceinline__ uint32_t elect_one_pred() {
    uint32_t pred;
    asm volatile(
        "{\n\t.reg .pred p;\n\telect.sync _|p, 0xFFFFFFFF;\n\tselp.b32 %0, 1, 0, p;\n\t}"
        : "=r"(pred));
    return pred;
}
__device__ __forceinline__ uint32_t f2_to_e4m3x2(float a, float b) {
    uint16_t r;
    asm("cvt.rn.satfinite.e4m3x2.f32 %0, %1, %2;" : "=h"(r) : "f"(b), "f"(a));
    return (uint32_t)r;
}
__device__ __forceinline__ float fp8_to_f(uint8_t v) {
    __half_raw h = __nv_cvt_fp8_to_halfraw((__nv_fp8_storage_t)v, __NV_E4M3);
    __half hh; *reinterpret_cast<__half_raw*>(&hh) = h;
    return __half2float(hh);
}
#define MBARRIER_INIT(mbar, count) \
    asm volatile("mbarrier.init.shared.b64 [%0], %1;" \
        :: "r"((uint32_t)(mbar)), "r"((uint32_t)(count)) : "memory")
#define MBARRIER_ARRIVE(mbar) \
    asm volatile("mbarrier.arrive.shared.b64 _, [%0];" \
        :: "r"((uint32_t)(mbar)) : "memory")
#define MBARRIER_EXPECT_TX(mbar, tx_bytes) \
    asm volatile("mbarrier.arrive.expect_tx.shared.b64 _, [%0], %1;" \
        :: "r"((uint32_t)(mbar)), "r"((uint32_t)(tx_bytes)) : "memory")
#define MBARRIER_WAIT_PARITY(mbar, phase_parity) do { \
    uint32_t _mbar = (uint32_t)(mbar); \
    uint32_t _parity = (uint32_t)(phase_parity); \
    uint32_t _done; \
    asm volatile( \
        "{\n\t.reg .pred p;\n\t" \
        "mbarrier.try_wait.parity.acquire.cta.shared::cta.b64 p, [%1], %2;\n\t" \
        "selp.b32 %0, 1, 0, p;\n\t}" \
        : "=r"(_done) : "r"(_mbar), "r"(_parity) : "memory"); \
    if (!_done) { \
        asm volatile( \
            "{\n\t.reg .pred P1;\n\t" \
            "WAIT_LOOP_%=:\n\t" \
            "mbarrier.try_wait.parity.acquire.cta.shared::cta.b64 P1, [%0], %1, 0x989680;\n\t" \
            "@P1 bra.uni WAIT_DONE_%=;\n\t" \
            "bra.uni WAIT_LOOP_%=;\n\t" \
            "WAIT_DONE_%=:\n\t}" \
            :: "r"(_mbar), "r"(_parity) : "memory"); \
    } \
} while (0)
#define TMA_LOAD_3D(smem_addr, map_ptr, cx, cy, cz, mbar) \
    asm volatile( \
        "cp.async.bulk.tensor.3d.shared::cta.global.tile.mbarrier::complete_tx::bytes " \
        "[%0], [%1, {%2, %3, %4}], [%5];" \
        :: "r"((uint32_t)(smem_addr)), "l"(map_ptr), "r"((int)(cx)), "r"((int)(cy)), \
           "r"((int)(cz)), "r"((uint32_t)(mbar)) : "memory")

#if USE_TCGEN05
#define TCGEN05_ALLOC(smem_addr, nCols) \
    asm volatile("tcgen05.alloc.cta_group::1.sync.aligned.shared::cta.b32 [%0], %1;" \
        :: "r"((uint32_t)(smem_addr)), "r"((uint32_t)(nCols)) : "memory")
#define TCGEN05_DEALLOC(tmem_addr, nCols) \
    asm volatile("tcgen05.dealloc.cta_group::1.sync.aligned.b32 %0, %1;" \
        :: "r"(tmem_addr), "r"((uint32_t)(nCols)))
#define TCGEN05_COMMIT(mbar) \
    asm volatile("tcgen05.commit.cta_group::1.mbarrier::arrive::one.shared::cluster.b64 [%0];" \
        :: "r"((uint32_t)(mbar)) : "memory")
#define TCGEN05_FENCE_AFTER() \
    asm volatile("tcgen05.fence::after_thread_sync;" ::: "memory")
#define TCGEN05_FENCE_BEFORE() \
    asm volatile("tcgen05.fence::before_thread_sync;" ::: "memory")
#define TCGEN05_WAIT_LD() \
    asm volatile("tcgen05.wait::ld.sync.aligned;" ::: "memory")
#define TCGEN05_LD_32X32B_X32(r, tmem_addr) \
    asm volatile( \
        "tcgen05.ld.sync.aligned.32x32b.x32.b32 " \
        "{%0, %1, %2, %3, %4, %5, %6, %7, " \
        " %8, %9, %10, %11, %12, %13, %14, %15, " \
        " %16, %17, %18, %19, %20, %21, %22, %23, " \
        " %24, %25, %26, %27, %28, %29, %30, %31}, [%32];" \
        : "=r"((r)[0]),  "=r"((r)[1]),  "=r"((r)[2]),  "=r"((r)[3]), \
          "=r"((r)[4]),  "=r"((r)[5]),  "=r"((r)[6]),  "=r"((r)[7]), \
          "=r"((r)[8]),  "=r"((r)[9]),  "=r"((r)[10]), "=r"((r)[11]), \
          "=r"((r)[12]), "=r"((r)[13]), "=r"((r)[14]), "=r"((r)[15]), \
          "=r"((r)[16]), "=r"((r)[17]), "=r"((r)[18]), "=r"((r)[19]), \
          "=r"((r)[20]), "=r"((r)[21]), "=r"((r)[22]), "=r"((r)[23]), \
          "=r"((r)[24]), "=r"((r)[25]), "=r"((r)[26]), "=r"((r)[27]), \
          "=r"((r)[28]), "=r"((r)[29]), "=r"((r)[30]), "=r"((r)[31]) \
        : "r"(tmem_addr))

// SW128 K-major smem descriptor (layout=2, version=1, SBO=64, LBO=1)
static constexpr uint64_t SMEM_DESC_BASE_SW128 =
    (uint64_t(2) << 61) | (uint64_t(1) << 46) | (uint64_t(64) << 32) | (uint64_t(1) << 16);
#define MAKE_SMEM_DESC(base_addr) \
    (SMEM_DESC_BASE_SW128 | ((uint64_t)((base_addr) >> 4) & 0x3FFF))

__device__ __forceinline__ void mma_f8_ss(uint32_t d, uint64_t ad, uint64_t bd,
                                          uint32_t idesc, uint32_t en) {
    asm volatile(
        "{\n\t.reg .pred p;\n\tsetp.ne.u32 p, %4, 0;\n\t"
        "tcgen05.mma.cta_group::1.kind::f8f6f4 [%0], %1, %2, %3, {%5, %5, %5, %5}, p;\n\t}"
        :: "r"(d), "l"(ad), "l"(bd), "r"(idesc), "r"(en), "r"(0u)
        : "memory");
}
#endif

// ---------------------------------------------------------------- prologue kernels
__global__ void k_styles(const float* __restrict__ w, const float* __restrict__ aff_w,
                         const float* __restrict__ aff_b) {
    int i = blockIdx.x;
    int b = threadIdx.x >> 5;
    int lane = threadIdx.x & 31;
    const float4* ar = (const float4*)(aff_w + (size_t)i * WDIM);
    const float4* wr = (const float4*)(w + (size_t)b * WDIM);
    float s = 0.f;
    for (int t = lane; t < WDIM / 4; t += 32) {
        float4 a = ar[t], ww = wr[t];
        s += a.x * ww.x + a.y * ww.y + a.z * ww.z + a.w * ww.w;
    }
    #pragma unroll
    for (int o = 16; o; o >>= 1) s += __shfl_xor_sync(0xffffffffu, s, o);
    if (lane == 0) g_styles[b * CIN + i] = s * 0.044194173824159216f + aff_b[i];
}

__global__ void k_prep_w(const float* __restrict__ weight) {
    const int o = blockIdx.x;
    const int tid = threadIdx.x;          // 128 threads
    const int lane = tid & 31;
    const int wrp = tid >> 5;
    __shared__ float red[8][128];
    const float* wr = weight + (size_t)o * CIN;
    float acc[8] = {0, 0, 0, 0, 0, 0, 0, 0};
    #pragma unroll
    for (int t = 0; t < CIN / 128; t++) {
        const int c = t * 128 + tid;
        const float wv = wr[c];
        g_wb[((size_t)(c >> 7) * COUT + o) * 128 + (c & 127)] =
            (uint8_t)f2_to_e4m3x2(wv, 0.f);
        const float w2 = wv * wv;
        #pragma unroll
        for (int b = 0; b < 8; b++) {
            const float s = g_styles[b * CIN + c];
            acc[b] += w2 * s * s;
        }
    }
    #pragma unroll
    for (int b = 0; b < 8; b++) red[b][tid] = acc[b];
    __syncthreads();
    #pragma unroll
    for (int h = 0; h < 2; h++) {
        const int b = wrp * 2 + h;
        float s = red[b][lane] + red[b][lane + 32] + red[b][lane + 64] + red[b][lane + 96];
        #pragma unroll
        for (int off = 16; off; off >>= 1) s += __shfl_xor_sync(0xffffffffu, s, off);
        if (lane == 0) g_dcoefs[b * COUT + o] = rsqrtf(s + 1e-8f);
    }
}

__global__ void k_mod(const float* __restrict__ x) {
    size_t idx = ((size_t)blockIdx.x * blockDim.x + threadIdx.x) * 4;
    int c = (int)(idx & (CIN - 1));
    int m = (int)(idx >> 10);
    int b = (int)(idx >> 22);
    float4 xv = *(const float4*)(x + idx);
    float4 sv = *(const float4*)(g_styles + b * CIN + c);
    uint32_t lo = f2_to_e4m3x2(xv.x * sv.x, xv.y * sv.y);
    uint32_t hi = f2_to_e4m3x2(xv.z * sv.z, xv.w * sv.w);
    *(uint32_t*)(g_xb + ((size_t)(c >> 7) * MTOT + m) * 128 + (c & 127)) = lo | (hi << 16);
}

// ---------------------------------------------------------------- GEMM (A-pinned, B-streamed)
__global__ void __launch_bounds__(192, 1)
k_gemm(const __grid_constant__ CUtensorMap tmA,
       const __grid_constant__ CUtensorMap tmB,
       const float* __restrict__ x, const float* __restrict__ bias,
       const float* __restrict__ ls, float* __restrict__ out) {
    extern __shared__ uint8_t dsm[];
    const int tid = threadIdx.x;
    const int wid = tid >> 5;
    const int lane = tid & 31;
    const int bn0 = blockIdx.x * GBNT;
    const int bm0 = blockIdx.y * GBM;
    const int batch = bm0 >> 12;

#if USE_TCGEN05
    __shared__ __align__(8) uint64_t s_full[BSTAGES], s_empty[BSTAGES];
    __shared__ __align__(8) uint64_t s_abar, s_done[2], s_free[2];
    __shared__ uint32_t s_tmem;
    __shared__ __align__(16) float s_bias[GBNT], s_ls[GBNT], s_dco[GBNT];

    const uint32_t base = (smem_u32(dsm) + 1023u) & ~1023u;
    const uint32_t apin = base;                    // 8 x 16KB A planes
    const uint32_t bring = base + A_PIN;           // 4 x 16KB B stages

    if (tid == 0) {
        #pragma unroll
        for (int s = 0; s < BSTAGES; s++) {
            MBARRIER_INIT(smem_u32(&s_full[s]), 1);
            MBARRIER_INIT(smem_u32(&s_empty[s]), 1);
        }
        MBARRIER_INIT(smem_u32(&s_abar), 1);
        MBARRIER_INIT(smem_u32(&s_done[0]), 1);
        MBARRIER_INIT(smem_u32(&s_done[1]), 1);
        MBARRIER_INIT(smem_u32(&s_free[0]), 128);
        MBARRIER_INIT(smem_u32(&s_free[1]), 128);
        asm volatile("fence.proxy.async.shared::cta;" ::: "memory");
    }
    if (wid == 0) TCGEN05_ALLOC(smem_u32(&s_tmem), 256);

    for (int n = tid; n < GBNT; n += 192) {
        s_bias[n] = bias[bn0 + n];
        s_ls[n]   = ls[bn0 + n];
        s_dco[n]  = g_dcoefs[batch * COUT + bn0 + n];
    }
    __syncthreads();
    const uint32_t tmem = s_tmem;

    if (wid == 4) {
        // ---------------- TMA producer: A once, then B stream ----------------
        if (elect_one_pred()) {
            MBARRIER_EXPECT_TX(smem_u32(&s_abar), A_PIN);
            #pragma unroll
            for (int kt = 0; kt < GNKT; kt++)
                TMA_LOAD_3D(apin + kt * 16384, &tmA, 0, bm0, kt, smem_u32(&s_abar));
            int pph = 1;
            int s = 0;
            for (int q = 0; q < NQ; q++) {
                for (int kt = 0; kt < GNKT; kt++) {
                    MBARRIER_WAIT_PARITY(smem_u32(&s_empty[s]), pph);
                    const uint32_t fb = smem_u32(&s_full[s]);
                    MBARRIER_EXPECT_TX(fb, B_STAGE);
                    TMA_LOAD_3D(bring + s * B_STAGE, &tmB, 0, bn0 + q * GBNQ, kt, fb);
                    if (++s == BSTAGES) { s = 0; pph ^= 1; }
                }
            }
        }
    } else if (wid == 5) {
        // ---------------- MMA issuer: 4 N-quarters into ping-pong TMEM halves ----------------
        if (elect_one_pred()) {
            MBARRIER_WAIT_PARITY(smem_u32(&s_abar), 0);   // A pinned
            int cph = 0;
            int s = 0;
            for (int q = 0; q < NQ; q++) {
                const int b = q & 1;
                if (q >= 2) {                              // wait for epilogue to free this half
                    MBARRIER_WAIT_PARITY(smem_u32(&s_free[b]), 0);
                }
                TCGEN05_FENCE_AFTER();
                const uint32_t dst = tmem + b * 128;
                for (int kt = 0; kt < GNKT; kt++) {
                    MBARRIER_WAIT_PARITY(smem_u32(&s_full[s]), cph);
                    const uint64_t ad = MAKE_SMEM_DESC(apin + kt * 16384);
                    const uint64_t bd = MAKE_SMEM_DESC(bring + s * B_STAGE);
                    #pragma unroll
                    for (int j = 0; j < 4; j++) {          // K=32 per MMA, +2 desc units per step
                        const uint32_t en = (kt | j) ? 1u : 0u;
                        mma_f8_ss(dst, ad + j * 2, bd + j * 2, IDESC_F8, en);
                    }
                    TCGEN05_COMMIT(smem_u32(&s_empty[s]));
                    if (++s == BSTAGES) { s = 0; cph ^= 1; }
                }
                TCGEN05_COMMIT(smem_u32(&s_done[b]));      // quarter q drains during quarter q+1
            }
        }
    } else if (wid < 4) {
        // ---------------- epilogue warps 0..3: one quarter at a time, pipelined ----------------
        const int gm = bm0 + wid * 32 + lane;
        const float* xr = x + (size_t)gm * COUT + bn0;
        float* orow = out + (size_t)gm * COUT + bn0;
        uint32_t t0[32], t1[32];
        float4 xb0[8], xb1[8];
        int phd[2] = {0, 0};

        #pragma unroll
        for (int q = 0; q < NQ; q++) {
            const int b = q & 1;
            const int nq0 = q * GBNQ;
            // prefetch first two 32-col chunks of this quarter (hides behind mainloop q)
            #pragma unroll
            for (int p = 0; p < 8; p++) xb0[p] = *(const float4*)(xr + nq0 + p * 4);
            #pragma unroll
            for (int p = 0; p < 8; p++) xb1[p] = *(const float4*)(xr + nq0 + 32 + p * 4);

            MBARRIER_WAIT_PARITY(smem_u32(&s_done[b]), phd[b]);
            phd[b] ^= 1;
            TCGEN05_FENCE_AFTER();
            const uint32_t src = tmem + b * 128;
            TCGEN05_LD_32X32B_X32(t0, src);

            #pragma unroll
            for (int c4 = 0; c4 < 4; c4++) {
                uint32_t* tc = (c4 & 1) ? t1 : t0;
                uint32_t* tn = (c4 & 1) ? t0 : t1;
                float4*   xc = (c4 & 1) ? xb1 : xb0;

                TCGEN05_WAIT_LD();
                if (c4 < 3)
                    TCGEN05_LD_32X32B_X32(tn, src + (c4 + 1) * 32);

                const int nb = nq0 + c4 * 32;
                #pragma unroll
                for (int j = 0; j < 32; j += 4) {
                    const int n = nb + j;
                    const float4 bi = *(const float4*)(s_bias + n);
                    const float4 lv = *(const float4*)(s_ls + n);
                    const float4 dc = *(const float4*)(s_dco + n);
                    const float4 xv = xc[j >> 2];
                    float y0 = __uint_as_float(tc[j + 0]) * dc.x + bi.x;
                    float y1 = __uint_as_float(tc[j + 1]) * dc.y + bi.y;
                    float y2 = __uint_as_float(tc[j + 2]) * dc.z + bi.z;
                    float y3 = __uint_as_float(tc[j + 3]) * dc.w + bi.w;
                    y0 = (y0 > 0.f ? y0 : 0.2f * y0) * 1.4142135623730951f;
                    y1 = (y1 > 0.f ? y1 : 0.2f * y1) * 1.4142135623730951f;
                    y2 = (y2 > 0.f ? y2 : 0.2f * y2) * 1.4142135623730951f;
                    y3 = (y3 > 0.f ? y3 : 0.2f * y3) * 1.4142135623730951f;
                    y0 = fminf(fmaxf(y0, -256.f), 256.f);
                    y1 = fminf(fmaxf(y1, -256.f), 256.f);
                    y2 = fminf(fmaxf(y2, -256.f), 256.f);
                    y3 = fminf(fmaxf(y3, -256.f), 256.f);
                    float4 o;
                    o.x = y0 * lv.x + xv.x;
                    o.y = y1 * lv.y + xv.y;
                    o.z = y2 * lv.z + xv.z;
                    o.w = y3 * lv.w + xv.w;
                    *(float4*)(orow + n) = o;
                }
                if (c4 < 2) {
                    const int n2 = nq0 + (c4 + 2) * 32;
                    #pragma unroll
                    for (int p = 0; p < 8; p++) xc[p] = *(const float4*)(xr + n2 + p * 4);
                }
            }
            if (q < 2) {
                TCGEN05_FENCE_BEFORE();
                MBARRIER_ARRIVE(smem_u32(&s_free[b]));     // release half for quarter q+2
            }
        }
    }

    __syncthreads();
    if (wid == 0) TCGEN05_DEALLOC(tmem, 256);

#else
    // ===== naive correctness fallback (plain-103 pass; never selected on GB300) =====
    for (int e = tid; e < GBM * GBNT; e += 192) {
        const int mi = e / GBNT, ni = e % GBNT;
        const int gm = bm0 + mi, gn = bn0 + ni;
        float acc = 0.f;
        for (int kt = 0; kt < GNKT; kt++) {
            const uint8_t* ar = g_xb + ((size_t)kt * MTOT + gm) * 128;
            const uint8_t* br = g_wb + ((size_t)kt * COUT + gn) * 128;
            for (int kk = 0; kk < 128; kk++)
                acc += fp8_to_f(ar[kk]) * fp8_to_f(br[kk]);
        }
        float y = acc * g_dcoefs[batch * COUT + gn] + bias[gn];
        y = (y > 0.f ? y : 0.2f * y) * 1.4142135623730951f;
        y = fminf(fmaxf(y, -256.f), 256.f);
        out[(size_t)gm * COUT + gn] = y * ls[gn] + x[(size_t)gm * COUT + gn];
    }
#endif
}

// ---------------------------------------------------------------- launch
typedef CUresult (*EncodeTiledFn)(
    CUtensorMap*, CUtensorMapDataType, cuuint32_t, void*,
    const cuuint64_t*, const cuuint64_t*, const cuuint32_t*, const cuuint32_t*,
    CUtensorMapInterleave, CUtensorMapSwizzle, CUtensorMapL2promotion,
    CUtensorMapFloatOOBfill);

extern "C" void kernel_launch(void* const* d_in, const int* in_sizes, int n_in,
                              void* d_out, int out_size) {
    const float* x      = (const float*)d_in[0];
    const float* w      = (const float*)d_in[1];
    const float* weight = (const float*)d_in[2];
    const float* bias   = (const float*)d_in[3];
    const float* aff_w  = (const float*)d_in[4];
    const float* aff_b  = (const float*)d_in[5];
    const float* ls     = (const float*)d_in[6];
    float* out = (float*)d_out;

    k_styles<<<CIN, 256>>>(w, aff_w, aff_b);
    k_prep_w<<<COUT, 128>>>(weight);
    k_mod<<<(int)((size_t)MTOT * CIN / 4 / 256), 256>>>(x);

    // tensormaps: 3D K-blocked fp8 — inner 128B, rows contiguous at 128B stride
    CUtensorMap tmA = {}, tmB = {};
    void* fn = nullptr;
    cudaDriverEntryPointQueryResult qr;
    cudaGetDriverEntryPointByVersion("cuTensorMapEncodeTiled", &fn, 12000,
                                     cudaEnableDefault, &qr);
    if (fn) {
        EncodeTiledFn encode = (EncodeTiledFn)fn;
        void *xb_ptr = nullptr, *wb_ptr = nullptr;
        cudaGetSymbolAddress(&xb_ptr, g_xb);
        cudaGetSymbolAddress(&wb_ptr, g_wb);
        {
            cuuint64_t dims[3] = {128, MTOT, GNKT};
            cuuint64_t str[2] = {128, (cuuint64_t)MTOT * 128};
            cuuint32_t box[3] = {128, GBM, 1};
            cuuint32_t es[3] = {1, 1, 1};
            encode(&tmA, CU_TENSOR_MAP_DATA_TYPE_UINT8, 3, xb_ptr, dims, str, box, es,
                   CU_TENSOR_MAP_INTERLEAVE_NONE, CU_TENSOR_MAP_SWIZZLE_128B,
                   CU_TENSOR_MAP_L2_PROMOTION_L2_128B, CU_TENSOR_MAP_FLOAT_OOB_FILL_NONE);
        }
        {
            cuuint64_t dims[3] = {128, COUT, GNKT};
            cuuint64_t str[2] = {128, (cuuint64_t)COUT * 128};
            cuuint32_t box[3] = {128, GBNQ, 1};
            cuuint32_t es[3] = {1, 1, 1};
            encode(&tmB, CU_TENSOR_MAP_DATA_TYPE_UINT8, 3, wb_ptr, dims, str, box, es,
                   CU_TENSOR_MAP_INTERLEAVE_NONE, CU_TENSOR_MAP_SWIZZLE_128B,
                   CU_TENSOR_MAP_L2_PROMOTION_L2_128B, CU_TENSOR_MAP_FLOAT_OOB_FILL_NONE);
        }
    }

    cudaFuncSetAttribute(k_gemm, cudaFuncAttributeMaxDynamicSharedMemorySize, DYN_SMEM);
    dim3 grid(COUT / GBNT, MTOT / GBM);
    k_gemm<<<grid, 192, DYN_SMEM>>>(tmA, tmB, x, bias, ls, out);
}

// round 14
// speedup vs baseline: 1.0612x; 1.0612x over previous
#include <cuda_runtime.h>
#include <cuda.h>
#include <cuda_bf16.h>
#include <cuda_fp8.h>
#include <cstdint>

#define MTOT 32768
#define CIN  1024
#define COUT 1024
#define WDIM 512

// ---- GEMM tiling: 128 x 256 output tile, 192 threads, 1 CTA/SM, FP8, split-N ----
// Cluster (2,1,1) along x: pair shares bm0 -> A multicast.
#define GBM 128
#define GBN 256
#define GBNH 128                     // N-half
#define GBK 128                      // 128 e4m3 = 128B = one SW128 atom row
#define GSTAGES 6
#define GNKT (CIN / GBK)             // 8 K-steps per half
#define AH_STAGE (GBM * 128)         // 16384 B
#define BH_STAGE (GBNH * 128)        // 16384 B
#define STAGE_BYTES (AH_STAGE + BH_STAGE)   // 32768
#define DYN_SMEM (1024 + GSTAGES * STAGE_BYTES)   // 197632

// idesc kind::f8f6f4: dtype=F32(1<<4), E4M3, N=128(16<<17), M=128(8<<24)
#define IDESC_F8 0x08200010u

#if defined(__CUDA_ARCH_FEAT_SM103_ALL) || defined(__CUDA_ARCH_FEAT_SM100_ALL)
#define USE_TCGEN05 1
#elif defined(__CUDA_ARCH_SPECIFIC__) && (__CUDA_ARCH_SPECIFIC__ >= 1000)
#define USE_TCGEN05 1
#elif defined(__CUDA_ARCH_FAMILY_SPECIFIC__) && (__CUDA_ARCH_FAMILY_SPECIFIC__ >= 1000)
#define USE_TCGEN05 1
#else
#define USE_TCGEN05 0
#endif

// Scratch (device globals — no allocation allowed)
__device__ __align__(1024) uint8_t g_xb[(size_t)MTOT * CIN];   // 32 MB e4m3
__device__ __align__(1024) uint8_t g_wb[(size_t)COUT * CIN];   // 1 MB e4m3
__device__ __align__(16) float g_styles[8 * CIN];
__device__ __align__(16) float g_dcoefs[8 * COUT];

// ---------------------------------------------------------------- helpers
__device__ __forceinline__ uint32_t smem_u32(const void* p) {
    uint32_t a;
    asm("{ .reg .u64 t; cvta.to.shared.u64 t, %1; cvt.u32.u64 %0, t; }" : "=r"(a) : "l"(p));
    return a;
}
__device__ __forceinline__ uint32_t elect_one_pred() {
    uint32_t pred;
    asm volatile(
        "{\n\t.reg .pred p;\n\telect.sync _|p, 0xFFFFFFFF;\n\tselp.b32 %0, 1, 0, p;\n\t}"
        : "=r"(pred));
    return pred;
}
__device__ __forceinline__ uint32_t f2_to_e4m3x2(float a, float b) {
    uint16_t r;
    asm("cvt.rn.satfinite.e4m3x2.f32 %0, %1, %2;" : "=h"(r) : "f"(b), "f"(a));
    return (uint32_t)r;
}
__device__ __forceinline__ float fp8_to_f(uint8_t v) {
    __half_raw h = __nv_cvt_fp8_to_halfraw((__nv_fp8_storage_t)v, __NV_E4M3);
    __half hh; *reinterpret_cast<__half_raw*>(&hh) = h;
    return __half2float(hh);
}
__device__ __forceinline__ uint32_t cluster_rank() {
    uint32_t r;
    asm("mov.u32 %0, %%cluster_ctarank;" : "=r"(r));
    return r;
}
#define CLUSTER_SYNC() do { \
    asm volatile("barrier.cluster.arrive.aligned;" ::: "memory"); \
    asm volatile("barrier.cluster.wait.aligned;" ::: "memory"); \
} while (0)
#define MBARRIER_INIT(mbar, count) \
    asm volatile("mbarrier.init.shared.b64 [%0], %1;" \
        :: "r"((uint32_t)(mbar)), "r"((uint32_t)(count)) : "memory")
#define MBARRIER_EXPECT_TX(mbar, tx_bytes) \
    asm volatile("mbarrier.arrive.expect_tx.shared.b64 _, [%0], %1;" \
        :: "r"((uint32_t)(mbar)), "r"((uint32_t)(tx_bytes)) : "memory")
#define MBARRIER_WAIT_PARITY(mbar, phase_parity) do { \
    uint32_t _mbar = (uint32_t)(mbar); \
    uint32_t _parity = (uint32_t)(phase_parity); \
    uint32_t _done; \
    asm volatile( \
        "{\n\t.reg .pred p;\n\t" \
        "mbarrier.try_wait.parity.acquire.cta.shared::cta.b64 p, [%1], %2;\n\t" \
        "selp.b32 %0, 1, 0, p;\n\t}" \
        : "=r"(_done) : "r"(_mbar), "r"(_parity) : "memory"); \
    if (!_done) { \
        asm volatile( \
            "{\n\t.reg .pred P1;\n\t" \
            "WAIT_LOOP_%=:\n\t" \
            "mbarrier.try_wait.parity.acquire.cta.shared::cta.b64 P1, [%0], %1, 0x989680;\n\t" \
            "@P1 bra.uni WAIT_DONE_%=;\n\t" \
            "bra.uni WAIT_LOOP_%=;\n\t" \
            "WAIT_DONE_%=:\n\t}" \
            :: "r"(_mbar), "r"(_parity) : "memory"); \
    } \
} while (0)
#define TMA_LOAD_3D(smem_addr, map_ptr, cx, cy, cz, mbar) \
    asm volatile( \
        "cp.async.bulk.tensor.3d.shared::cta.global.tile.mbarrier::complete_tx::bytes " \
        "[%0], [%1, {%2, %3, %4}], [%5];" \
        :: "r"((uint32_t)(smem_addr)), "l"(map_ptr), "r"((int)(cx)), "r"((int)(cy)), \
           "r"((int)(cz)), "r"((uint32_t)(mbar)) : "memory")
#define TMA_LOAD_3D_MC(smem_addr, map_ptr, cx, cy, cz, mbar, mask) \
    asm volatile( \
        "cp.async.bulk.tensor.3d.shared::cluster.global.tile.mbarrier::complete_tx::bytes.multicast::cluster " \
        "[%0], [%1, {%2, %3, %4}], [%5], %6;" \
        :: "r"((uint32_t)(smem_addr)), "l"(map_ptr), "r"((int)(cx)), "r"((int)(cy)), \
           "r"((int)(cz)), "r"((uint32_t)(mbar)), "h"((uint16_t)(mask)) : "memory")

#if USE_TCGEN05
#define TCGEN05_ALLOC(smem_addr, nCols) \
    asm volatile("tcgen05.alloc.cta_group::1.sync.aligned.shared::cta.b32 [%0], %1;" \
        :: "r"((uint32_t)(smem_addr)), "r"((uint32_t)(nCols)) : "memory")
#define TCGEN05_DEALLOC(tmem_addr, nCols) \
    asm volatile("tcgen05.dealloc.cta_group::1.sync.aligned.b32 %0, %1;" \
        :: "r"(tmem_addr), "r"((uint32_t)(nCols)))
#define TCGEN05_COMMIT(mbar) \
    asm volatile("tcgen05.commit.cta_group::1.mbarrier::arrive::one.shared::cluster.b64 [%0];" \
        :: "r"((uint32_t)(mbar)) : "memory")
#define TCGEN05_COMMIT_MC(mbar, mask) \
    asm volatile("tcgen05.commit.cta_group::1.mbarrier::arrive::one.shared::cluster.multicast::cluster.b64 [%0], %1;" \
        :: "r"((uint32_t)(mbar)), "h"((uint16_t)(mask)) : "memory")
#define TCGEN05_FENCE_AFTER() \
    asm volatile("tcgen05.fence::after_thread_sync;" ::: "memory")
#define TCGEN05_WAIT_LD() \
    asm volatile("tcgen05.wait::ld.sync.aligned;" ::: "memory")
#define TCGEN05_LD_32X32B_X32(r, tmem_addr) \
    asm volatile( \
        "tcgen05.ld.sync.aligned.32x32b.x32.b32 " \
        "{%0, %1, %2, %3, %4, %5, %6, %7, " \
        " %8, %9, %10, %11, %12, %13, %14, %15, " \
        " %16, %17, %18, %19, %20, %21, %22, %23, " \
        " %24, %25, %26, %27, %28, %29, %30, %31}, [%32];" \
        : "=r"((r)[0]),  "=r"((r)[1]),  "=r"((r)[2]),  "=r"((r)[3]), \
          "=r"((r)[4]),  "=r"((r)[5]),  "=r"((r)[6]),  "=r"((r)[7]), \
          "=r"((r)[8]),  "=r"((r)[9]),  "=r"((r)[10]), "=r"((r)[11]), \
          "=r"((r)[12]), "=r"((r)[13]), "=r"((r)[14]), "=r"((r)[15]), \
          "=r"((r)[16]), "=r"((r)[17]), "=r"((r)[18]), "=r"((r)[19]), \
          "=r"((r)[20]), "=r"((r)[21]), "=r"((r)[22]), "=r"((r)[23]), \
          "=r"((r)[24]), "=r"((r)[25]), "=r"((r)[26]), "=r"((r)[27]), \
          "=r"((r)[28]), "=r"((r)[29]), "=r"((r)[30]), "=r"((r)[31]) \
        : "r"(tmem_addr))

// SW128 K-major smem descriptor (layout=2, version=1, SBO=64, LBO=1)
static constexpr uint64_t SMEM_DESC_BASE_SW128 =
    (uint64_t(2) << 61) | (uint64_t(1) << 46) | (uint64_t(64) << 32) | (uint64_t(1) << 16);
#define MAKE_SMEM_DESC(base_addr) \
    (SMEM_DESC_BASE_SW128 | ((uint64_t)((base_addr) >> 4) & 0x3FFF))

__device__ __forceinline__ void mma_f8_ss(uint32_t d, uint64_t ad, uint64_t bd,
                                          uint32_t idesc, uint32_t en) {
    asm volatile(
        "{\n\t.reg .pred p;\n\tsetp.ne.u32 p, %4, 0;\n\t"
        "tcgen05.mma.cta_group::1.kind::f8f6f4 [%0], %1, %2, %3, {%5, %5, %5, %5}, p;\n\t}"
        :: "r"(d), "l"(ad), "l"(bd), "r"(idesc), "r"(en), "r"(0u)
        : "memory");
}
#endif

// ---------------------------------------------------------------- prologue kernels
__global__ void k_styles(const float* __restrict__ w, const float* __restrict__ aff_w,
                         const float* __restrict__ aff_b) {
    int i = blockIdx.x;
    int b = threadIdx.x >> 5;
    int lane = threadIdx.x & 31;
    const float4* ar = (const float4*)(aff_w + (size_t)i * WDIM);
    const float4* wr = (const float4*)(w + (size_t)b * WDIM);
    float s = 0.f;
    for (int t = lane; t < WDIM / 4; t += 32) {
        float4 a = ar[t], ww = wr[t];
        s += a.x * ww.x + a.y * ww.y + a.z * ww.z + a.w * ww.w;
    }
    #pragma unroll
    for (int o = 16; o; o >>= 1) s += __shfl_xor_sync(0xffffffffu, s, o);
    if (lane == 0) g_styles[b * CIN + i] = s * 0.044194173824159216f + aff_b[i];
}

// Fused: blocks [0, COUT) do weight convert + dcoefs; blocks [COUT, ...) do x modulation.
__global__ void k_prep(const float* __restrict__ weight, const float* __restrict__ x) {
    const int tid = threadIdx.x;          // 256 threads
    if (blockIdx.x < COUT) {
        const int o = blockIdx.x;
        const int lane = tid & 31;
        const int wrp = tid >> 5;         // 8 warps -> 8 batches
        __shared__ float red[8][256];
        const float* wr = weight + (size_t)o * CIN;
        float acc[8] = {0, 0, 0, 0, 0, 0, 0, 0};
        #pragma unroll
        for (int t = 0; t < CIN / 256; t++) {
            const int c = t * 256 + tid;
            const float wv = wr[c];
            g_wb[((size_t)(c >> 7) * COUT + o) * 128 + (c & 127)] =
                (uint8_t)f2_to_e4m3x2(wv, 0.f);
            const float w2 = wv * wv;
            #pragma unroll
            for (int b = 0; b < 8; b++) {
                const float s = g_styles[b * CIN + c];
                acc[b] += w2 * s * s;
            }
        }
        #pragma unroll
        for (int b = 0; b < 8; b++) red[b][tid] = acc[b];
        __syncthreads();
        float s = 0.f;
        #pragma unroll
        for (int k = 0; k < 8; k++) s += red[wrp][lane + k * 32];
        #pragma unroll
        for (int off = 16; off; off >>= 1) s += __shfl_xor_sync(0xffffffffu, s, off);
        if (lane == 0) g_dcoefs[wrp * COUT + o] = rsqrtf(s + 1e-8f);
    } else {
        size_t idx = ((size_t)(blockIdx.x - COUT) * 256 + tid) * 4;
        int c = (int)(idx & (CIN - 1));
        int m = (int)(idx >> 10);
        int b = (int)(idx >> 22);
        float4 xv = *(const float4*)(x + idx);
        float4 sv = *(const float4*)(g_styles + b * CIN + c);
        uint32_t lo = f2_to_e4m3x2(xv.x * sv.x, xv.y * sv.y);
        uint32_t hi = f2_to_e4m3x2(xv.z * sv.z, xv.w * sv.w);
        *(uint32_t*)(g_xb + ((size_t)(c >> 7) * MTOT + m) * 128 + (c & 127)) = lo | (hi << 16);
    }
}

// ---------------------------------------------------------------- GEMM (split-N, cluster-2 A-multicast)
__global__ void __launch_bounds__(192, 1) __cluster_dims__(2, 1, 1)
k_gemm(const __grid_constant__ CUtensorMap tmA,
       const __grid_constant__ CUtensorMap tmB,
       const float* __restrict__ x, const float* __restrict__ bias,
       const float* __restrict__ ls, float* __restrict__ out) {
    extern __shared__ uint8_t dsm[];
    const int tid = threadIdx.x;
    const int wid = tid >> 5;
    const int lane = tid & 31;
    const int bn0 = blockIdx.x * GBN;
    const int bm0 = blockIdx.y * GBM;
    const int batch = bm0 >> 12;

#if USE_TCGEN05
    __shared__ __align__(8) uint64_t s_full[GSTAGES], s_empty[GSTAGES], s_done[2];
    __shared__ uint32_t s_tmem;
    __shared__ __align__(16) float s_bias[GBN], s_ls[GBN], s_dco[GBN];

    const uint32_t base = (smem_u32(dsm) + 1023u) & ~1023u;
    const uint32_t rank = cluster_rank();

    if (tid == 0) {
        #pragma unroll
        for (int s = 0; s < GSTAGES; s++) {
            MBARRIER_INIT(smem_u32(&s_full[s]), 1);
            MBARRIER_INIT(smem_u32(&s_empty[s]), 2);   // both pair-consumers must release
        }
        MBARRIER_INIT(smem_u32(&s_done[0]), 1);
        MBARRIER_INIT(smem_u32(&s_done[1]), 1);
        asm volatile("fence.proxy.async.shared::cta;" ::: "memory");
    }
    if (wid == 0) TCGEN05_ALLOC(smem_u32(&s_tmem), 256);

    for (int n = tid; n < GBN; n += 192) {
        s_bias[n] = bias[bn0 + n];
        s_ls[n]   = ls[bn0 + n];
        s_dco[n]  = g_dcoefs[batch * COUT + bn0 + n];
    }
    __syncthreads();
    CLUSTER_SYNC();              // peer barriers must be live before multicast targets them
    const uint32_t tmem = s_tmem;

    if (wid == 4) {
        // ------- TMA producer: rank0 multicasts shared A; each rank loads own B -------
        if (elect_one_pred()) {
            int pph = 1;
            int s = 0;
            #pragma unroll
            for (int h = 0; h < 2; h++) {
                for (int kt = 0; kt < GNKT; kt++) {
                    MBARRIER_WAIT_PARITY(smem_u32(&s_empty[s]), pph);
                    const uint32_t stg = base + s * STAGE_BYTES;
                    const uint32_t fb = smem_u32(&s_full[s]);
                    MBARRIER_EXPECT_TX(fb, STAGE_BYTES);
                    if (rank == 0)
                        TMA_LOAD_3D_MC(stg, &tmA, 0, bm0, kt, fb, 0x3);   // A -> both CTAs
                    TMA_LOAD_3D(stg + AH_STAGE, &tmB, 0, bn0 + h * GBNH, kt, fb);
                    if (++s == GSTAGES) { s = 0; pph ^= 1; }
                }
            }
        }
    } else if (wid == 5) {
        // ------- MMA issuer: commit-multicast releases the stage in BOTH CTAs -------
        if (elect_one_pred()) {
            int cph = 0;
            int s = 0;
            #pragma unroll
            for (int h = 0; h < 2; h++) {
                const uint32_t dst = tmem + h * 128;
                for (int kt = 0; kt < GNKT; kt++) {
                    MBARRIER_WAIT_PARITY(smem_u32(&s_full[s]), cph);
                    const uint32_t stg = base + s * STAGE_BYTES;
                    const uint64_t ad = MAKE_SMEM_DESC(stg);
                    const uint64_t bd = MAKE_SMEM_DESC(stg + AH_STAGE);
                    #pragma unroll
                    for (int j = 0; j < 4; j++) {   // K=32 e4m3 per MMA, +2 desc units per step
                        const uint32_t en = (kt | j) ? 1u : 0u;
                        mma_f8_ss(dst, ad + j * 2, bd + j * 2, IDESC_F8, en);
                    }
                    TCGEN05_COMMIT_MC(smem_u32(&s_empty[s]), 0x3);
                    if (++s == GSTAGES) { s = 0; cph ^= 1; }
                }
                TCGEN05_COMMIT(smem_u32(&s_done[h]));
            }
        }
    } else if (wid < 4) {
        // ------- epilogue warps 0..3: drains half 0 during half 1's mainloop -------
        const int gm = bm0 + wid * 32 + lane;
        const float* xr = x + (size_t)gm * COUT + bn0;
        float* orow = out + (size_t)gm * COUT + bn0;

        float4 xb0[8], xb1[8];
        #pragma unroll
        for (int q = 0; q < 8; q++) xb0[q] = *(const float4*)(xr + q * 4);
        #pragma unroll
        for (int q = 0; q < 8; q++) xb1[q] = *(const float4*)(xr + 32 + q * 4);

        uint32_t t0[32], t1[32];

        #pragma unroll
        for (int h = 0; h < 2; h++) {
            MBARRIER_WAIT_PARITY(smem_u32(&s_done[h]), 0);
            TCGEN05_FENCE_AFTER();
            TCGEN05_LD_32X32B_X32(t0, tmem + (h * 4) * 32);

            #pragma unroll
            for (int c4 = 0; c4 < 4; c4++) {
                const int ch = h * 4 + c4;
                uint32_t* tc = (ch & 1) ? t1 : t0;
                uint32_t* tn = (ch & 1) ? t0 : t1;
                float4*   xc = (ch & 1) ? xb1 : xb0;

                TCGEN05_WAIT_LD();
                if (c4 < 3)
                    TCGEN05_LD_32X32B_X32(tn, tmem + (ch + 1) * 32);

                const int nb = ch * 32;
                #pragma unroll
                for (int j = 0; j < 32; j += 4) {
                    const int n = nb + j;
                    const float4 bi = *(const float4*)(s_bias + n);
                    const float4 lv = *(const float4*)(s_ls + n);
                    const float4 dc = *(const float4*)(s_dco + n);
                    const float4 xv = xc[j >> 2];
                    float y0 = __uint_as_float(tc[j + 0]) * dc.x + bi.x;
                    float y1 = __uint_as_float(tc[j + 1]) * dc.y + bi.y;
                    float y2 = __uint_as_float(tc[j + 2]) * dc.z + bi.z;
                    float y3 = __uint_as_float(tc[j + 3]) * dc.w + bi.w;
                    y0 = (y0 > 0.f ? y0 : 0.2f * y0) * 1.4142135623730951f;
                    y1 = (y1 > 0.f ? y1 : 0.2f * y1) * 1.4142135623730951f;
                    y2 = (y2 > 0.f ? y2 : 0.2f * y2) * 1.4142135623730951f;
                    y3 = (y3 > 0.f ? y3 : 0.2f * y3) * 1.4142135623730951f;
                    y0 = fminf(fmaxf(y0, -256.f), 256.f);
                    y1 = fminf(fmaxf(y1, -256.f), 256.f);
                    y2 = fminf(fmaxf(y2, -256.f), 256.f);
                    y3 = fminf(fmaxf(y3, -256.f), 256.f);
                    float4 o;
                    o.x = y0 * lv.x + xv.x;
                    o.y = y1 * lv.y + xv.y;
                    o.z = y2 * lv.z + xv.z;
                    o.w = y3 * lv.w + xv.w;
                    *(float4*)(orow + n) = o;
                }
                if (ch < 6) {
                    const int n2 = (ch + 2) * 32;
                    #pragma unroll
                    for (int q = 0; q < 8; q++) xc[q] = *(const float4*)(xr + n2 + q * 4);
                }
            }
        }
    }

    __syncthreads();
    if (wid == 0) TCGEN05_DEALLOC(tmem, 256);
    CLUSTER_SYNC();              // no CTA exits while peer multicast may be in flight

#else
    // ===== naive correctness fallback (plain-103 pass; never selected on GB300) =====
    for (int e = tid; e < GBM * GBN; e += 192) {
        const int mi = e / GBN, ni = e % GBN;
        const int gm = bm0 + mi, gn = bn0 + ni;
        float acc = 0.f;
        for (int kt = 0; kt < GNKT; kt++) {
            const uint8_t* ar = g_xb + ((size_t)kt * MTOT + gm) * 128;
            const uint8_t* br = g_wb + ((size_t)kt * COUT + gn) * 128;
            for (int kk = 0; kk < 128; kk++)
                acc += fp8_to_f(ar[kk]) * fp8_to_f(br[kk]);
        }
        float y = acc * g_dcoefs[batch * COUT + gn] + bias[gn];
        y = (y > 0.f ? y : 0.2f * y) * 1.4142135623730951f;
        y = fminf(fmaxf(y, -256.f), 256.f);
        out[(size_t)gm * COUT + gn] = y * ls[gn] + x[(size_t)gm * COUT + gn];
    }
#endif
}

// ---------------------------------------------------------------- launch
typedef CUresult (*EncodeTiledFn)(
    CUtensorMap*, CUtensorMapDataType, cuuint32_t, void*,
    const cuuint64_t*, const cuuint64_t*, const cuuint32_t*, const cuuint32_t*,
    CUtensorMapInterleave, CUtensorMapSwizzle, CUtensorMapL2promotion,
    CUtensorMapFloatOOBfill);

extern "C" void kernel_launch(void* const* d_in, const int* in_sizes, int n_in,
                              void* d_out, int out_size) {
    const float* x      = (const float*)d_in[0];
    const float* w      = (const float*)d_in[1];
    const float* weight = (const float*)d_in[2];
    const float* bias   = (const float*)d_in[3];
    const float* aff_w  = (const float*)d_in[4];
    const float* aff_b  = (const float*)d_in[5];
    const float* ls     = (const float*)d_in[6];
    float* out = (float*)d_out;

    k_styles<<<CIN, 256>>>(w, aff_w, aff_b);
    k_prep<<<COUT + (int)((size_t)MTOT * CIN / 4 / 256), 256>>>(weight, x);

    // tensormaps: 3D K-blocked fp8 — inner 128B, rows contiguous at 128B stride
    CUtensorMap tmA = {}, tmB = {};
    void* fn = nullptr;
    cudaDriverEntryPointQueryResult qr;
    cudaGetDriverEntryPointByVersion("cuTensorMapEncodeTiled", &fn, 12000,
                                     cudaEnableDefault, &qr);
    if (fn) {
        EncodeTiledFn encode = (EncodeTiledFn)fn;
        void *xb_ptr = nullptr, *wb_ptr = nullptr;
        cudaGetSymbolAddress(&xb_ptr, g_xb);
        cudaGetSymbolAddress(&wb_ptr, g_wb);
        {
            cuuint64_t dims[3] = {128, MTOT, GNKT};
            cuuint64_t str[2] = {128, (cuuint64_t)MTOT * 128};
            cuuint32_t box[3] = {128, GBM, 1};
            cuuint32_t es[3] = {1, 1, 1};
            encode(&tmA, CU_TENSOR_MAP_DATA_TYPE_UINT8, 3, xb_ptr, dims, str, box, es,
                   CU_TENSOR_MAP_INTERLEAVE_NONE, CU_TENSOR_MAP_SWIZZLE_128B,
                   CU_TENSOR_MAP_L2_PROMOTION_L2_128B, CU_TENSOR_MAP_FLOAT_OOB_FILL_NONE);
        }
        {
            cuuint64_t dims[3] = {128, COUT, GNKT};
            cuuint64_t str[2] = {128, (cuuint64_t)COUT * 128};
            cuuint32_t box[3] = {128, GBNH, 1};
            cuuint32_t es[3] = {1, 1, 1};
            encode(&tmB, CU_TENSOR_MAP_DATA_TYPE_UINT8, 3, wb_ptr, dims, str, box, es,
                   CU_TENSOR_MAP_INTERLEAVE_NONE, CU_TENSOR_MAP_SWIZZLE_128B,
                   CU_TENSOR_MAP_L2_PROMOTION_L2_128B, CU_TENSOR_MAP_FLOAT_OOB_FILL_NONE);
        }
    }

    cudaFuncSetAttribute(k_gemm, cudaFuncAttributeMaxDynamicSharedMemorySize, DYN_SMEM);
    dim3 grid(COUT / GBN, MTOT / GBM);
    k_gemm<<<grid, 192, DYN_SMEM>>>(tmA, tmB, x, bias, ls, out);
}

// round 15
// speedup vs baseline: 1.1199x; 1.0553x over previous
#include <cuda_runtime.h>
#include <cuda.h>
#include <cuda_bf16.h>
#include <cuda_fp8.h>
#include <cstdint>

#define MTOT 32768
#define CIN  1024
#define COUT 1024
#define WDIM 512

// ---- GEMM tiling: 128 x 256 output tile, 192 threads, 1 CTA/SM, FP8, split-N ----
#define GBM 128
#define GBN 256
#define GBNH 128                     // N-half
#define GBK 128                      // 128 e4m3 = 128B = one SW128 atom row
#define GSTAGES 6
#define GNKT (CIN / GBK)             // 8 K-steps per half
#define AH_STAGE (GBM * 128)         // 16384 B
#define BH_STAGE (GBNH * 128)        // 16384 B
#define STAGE_BYTES (AH_STAGE + BH_STAGE)   // 32768
#define DYN_SMEM (1024 + GSTAGES * STAGE_BYTES)   // 197632

// idesc kind::f8f6f4: dtype=F32(1<<4), E4M3, N=128(16<<17), M=128(8<<24)
#define IDESC_F8 0x08200010u

#if defined(__CUDA_ARCH_FEAT_SM103_ALL) || defined(__CUDA_ARCH_FEAT_SM100_ALL)
#define USE_TCGEN05 1
#elif defined(__CUDA_ARCH_SPECIFIC__) && (__CUDA_ARCH_SPECIFIC__ >= 1000)
#define USE_TCGEN05 1
#elif defined(__CUDA_ARCH_FAMILY_SPECIFIC__) && (__CUDA_ARCH_FAMILY_SPECIFIC__ >= 1000)
#define USE_TCGEN05 1
#else
#define USE_TCGEN05 0
#endif

// Scratch (device globals — no allocation allowed)
// K-BLOCKED fp8 layouts: xb[(kt*MTOT + m)*128 + k%128], wb[(kt*COUT + o)*128 + k%128]
__device__ __align__(1024) uint8_t g_xb[(size_t)MTOT * CIN];   // 32 MB e4m3
__device__ __align__(1024) uint8_t g_wb[(size_t)COUT * CIN];   // 1 MB e4m3
__device__ __align__(16) float g_styles[8 * CIN];
__device__ __align__(16) float g_dcoefs[8 * COUT];

// ---------------------------------------------------------------- helpers
__device__ __forceinline__ uint32_t smem_u32(const void* p) {
    uint32_t a;
    asm("{ .reg .u64 t; cvta.to.shared.u64 t, %1; cvt.u32.u64 %0, t; }" : "=r"(a) : "l"(p));
    return a;
}
__device__ __forceinline__ uint32_t elect_one_pred() {
    uint32_t pred;
    asm volatile(
        "{\n\t.reg .pred p;\n\telect.sync _|p, 0xFFFFFFFF;\n\tselp.b32 %0, 1, 0, p;\n\t}"
        : "=r"(pred));
    return pred;
}
__device__ __forceinline__ uint32_t f2_to_e4m3x2(float a, float b) {
    uint16_t r;
    asm("cvt.rn.satfinite.e4m3x2.f32 %0, %1, %2;" : "=h"(r) : "f"(b), "f"(a));
    return (uint32_t)r;
}
__device__ __forceinline__ float fp8_to_f(uint8_t v) {
    __half_raw h = __nv_cvt_fp8_to_halfraw((__nv_fp8_storage_t)v, __NV_E4M3);
    __half hh; *reinterpret_cast<__half_raw*>(&hh) = h;
    return __half2float(hh);
}
#define MBARRIER_INIT(mbar, count) \
    asm volatile("mbarrier.init.shared.b64 [%0], %1;" \
        :: "r"((uint32_t)(mbar)), "r"((uint32_t)(count)) : "memory")
#define MBARRIER_EXPECT_TX(mbar, tx_bytes) \
    asm volatile("mbarrier.arrive.expect_tx.shared.b64 _, [%0], %1;" \
        :: "r"((uint32_t)(mbar)), "r"((uint32_t)(tx_bytes)) : "memory")
#define MBARRIER_WAIT_PARITY(mbar, phase_parity) do { \
    uint32_t _mbar = (uint32_t)(mbar); \
    uint32_t _parity = (uint32_t)(phase_parity); \
    uint32_t _done; \
    asm volatile( \
        "{\n\t.reg .pred p;\n\t" \
        "mbarrier.try_wait.parity.acquire.cta.shared::cta.b64 p, [%1], %2;\n\t" \
        "selp.b32 %0, 1, 0, p;\n\t}" \
        : "=r"(_done) : "r"(_mbar), "r"(_parity) : "memory"); \
    if (!_done) { \
        asm volatile( \
            "{\n\t.reg .pred P1;\n\t" \
            "WAIT_LOOP_%=:\n\t" \
            "mbarrier.try_wait.parity.acquire.cta.shared::cta.b64 P1, [%0], %1, 0x989680;\n\t" \
            "@P1 bra.uni WAIT_DONE_%=;\n\t" \
            "bra.uni WAIT_LOOP_%=;\n\t" \
            "WAIT_DONE_%=:\n\t}" \
            :: "r"(_mbar), "r"(_parity) : "memory"); \
    } \
} while (0)
#define TMA_LOAD_3D(smem_addr, map_ptr, cx, cy, cz, mbar) \
    asm volatile( \
        "cp.async.bulk.tensor.3d.shared::cta.global.tile.mbarrier::complete_tx::bytes " \
        "[%0], [%1, {%2, %3, %4}], [%5];" \
        :: "r"((uint32_t)(smem_addr)), "l"(map_ptr), "r"((int)(cx)), "r"((int)(cy)), \
           "r"((int)(cz)), "r"((uint32_t)(mbar)) : "memory")

#if USE_TCGEN05
#define TCGEN05_ALLOC(smem_addr, nCols) \
    asm volatile("tcgen05.alloc.cta_group::1.sync.aligned.shared::cta.b32 [%0], %1;" \
        :: "r"((uint32_t)(smem_addr)), "r"((uint32_t)(nCols)) : "memory")
#define TCGEN05_DEALLOC(tmem_addr, nCols) \
    asm volatile("tcgen05.dealloc.cta_group::1.sync.aligned.b32 %0, %1;" \
        :: "r"(tmem_addr), "r"((uint32_t)(nCols)))
#define TCGEN05_COMMIT(mbar) \
    asm volatile("tcgen05.commit.cta_group::1.mbarrier::arrive::one.shared::cluster.b64 [%0];" \
        :: "r"((uint32_t)(mbar)) : "memory")
#define TCGEN05_FENCE_AFTER() \
    asm volatile("tcgen05.fence::after_thread_sync;" ::: "memory")
#define TCGEN05_WAIT_LD() \
    asm volatile("tcgen05.wait::ld.sync.aligned;" ::: "memory")
#define TCGEN05_LD_32X32B_X32(r, tmem_addr) \
    asm volatile( \
        "tcgen05.ld.sync.aligned.32x32b.x32.b32 " \
        "{%0, %1, %2, %3, %4, %5, %6, %7, " \
        " %8, %9, %10, %11, %12, %13, %14, %15, " \
        " %16, %17, %18, %19, %20, %21, %22, %23, " \
        " %24, %25, %26, %27, %28, %29, %30, %31}, [%32];" \
        : "=r"((r)[0]),  "=r"((r)[1]),  "=r"((r)[2]),  "=r"((r)[3]), \
          "=r"((r)[4]),  "=r"((r)[5]),  "=r"((r)[6]),  "=r"((r)[7]), \
          "=r"((r)[8]),  "=r"((r)[9]),  "=r"((r)[10]), "=r"((r)[11]), \
          "=r"((r)[12]), "=r"((r)[13]), "=r"((r)[14]), "=r"((r)[15]), \
          "=r"((r)[16]), "=r"((r)[17]), "=r"((r)[18]), "=r"((r)[19]), \
          "=r"((r)[20]), "=r"((r)[21]), "=r"((r)[22]), "=r"((r)[23]), \
          "=r"((r)[24]), "=r"((r)[25]), "=r"((r)[26]), "=r"((r)[27]), \
          "=r"((r)[28]), "=r"((r)[29]), "=r"((r)[30]), "=r"((r)[31]) \
        : "r"(tmem_addr))

// SW128 K-major smem descriptor (layout=2, version=1, SBO=64, LBO=1)
static constexpr uint64_t SMEM_DESC_BASE_SW128 =
    (uint64_t(2) << 61) | (uint64_t(1) << 46) | (uint64_t(64) << 32) | (uint64_t(1) << 16);
#define MAKE_SMEM_DESC(base_addr) \
    (SMEM_DESC_BASE_SW128 | ((uint64_t)((base_addr) >> 4) & 0x3FFF))

__device__ __forceinline__ void mma_f8_ss(uint32_t d, uint64_t ad, uint64_t bd,
                                          uint32_t idesc, uint32_t en) {
    asm volatile(
        "{\n\t.reg .pred p;\n\tsetp.ne.u32 p, %4, 0;\n\t"
        "tcgen05.mma.cta_group::1.kind::f8f6f4 [%0], %1, %2, %3, {%5, %5, %5, %5}, p;\n\t}"
        :: "r"(d), "l"(ad), "l"(bd), "r"(idesc), "r"(en), "r"(0u)
        : "memory");
}
#endif

// ---------------------------------------------------------------- prologue kernels
__global__ void k_styles(const float* __restrict__ w, const float* __restrict__ aff_w,
                         const float* __restrict__ aff_b) {
    int i = blockIdx.x;
    int b = threadIdx.x >> 5;
    int lane = threadIdx.x & 31;
    const float4* ar = (const float4*)(aff_w + (size_t)i * WDIM);
    const float4* wr = (const float4*)(w + (size_t)b * WDIM);
    float s = 0.f;
    for (int t = lane; t < WDIM / 4; t += 32) {
        float4 a = ar[t], ww = wr[t];
        s += a.x * ww.x + a.y * ww.y + a.z * ww.z + a.w * ww.w;
    }
    #pragma unroll
    for (int o = 16; o; o >>= 1) s += __shfl_xor_sync(0xffffffffu, s, o);
    if (lane == 0) g_styles[b * CIN + i] = s * 0.044194173824159216f + aff_b[i];
}

// Fused: blocks [0, COUT) do weight convert + dcoefs; blocks [COUT, ...) do x modulation.
__global__ void k_prep(const float* __restrict__ weight, const float* __restrict__ x) {
    const int tid = threadIdx.x;          // 256 threads
    if (blockIdx.x < COUT) {
        const int o = blockIdx.x;
        const int lane = tid & 31;
        const int wrp = tid >> 5;         // 8 warps -> 8 batches
        __shared__ float red[8][256];
        const float* wr = weight + (size_t)o * CIN;
        float acc[8] = {0, 0, 0, 0, 0, 0, 0, 0};
        #pragma unroll
        for (int t = 0; t < CIN / 256; t++) {
            const int c = t * 256 + tid;
            const float wv = wr[c];
            g_wb[((size_t)(c >> 7) * COUT + o) * 128 + (c & 127)] =
                (uint8_t)f2_to_e4m3x2(wv, 0.f);
            const float w2 = wv * wv;
            #pragma unroll
            for (int b = 0; b < 8; b++) {
                const float s = g_styles[b * CIN + c];
                acc[b] += w2 * s * s;
            }
        }
        #pragma unroll
        for (int b = 0; b < 8; b++) red[b][tid] = acc[b];
        __syncthreads();
        float s = 0.f;
        #pragma unroll
        for (int k = 0; k < 8; k++) s += red[wrp][lane + k * 32];
        #pragma unroll
        for (int off = 16; off; off >>= 1) s += __shfl_xor_sync(0xffffffffu, s, off);
        if (lane == 0) g_dcoefs[wrp * COUT + o] = rsqrtf(s + 1e-8f);
    } else {
        size_t idx = ((size_t)(blockIdx.x - COUT) * 256 + tid) * 4;
        int c = (int)(idx & (CIN - 1));
        int m = (int)(idx >> 10);
        int b = (int)(idx >> 22);
        float4 xv = *(const float4*)(x + idx);
        float4 sv = *(const float4*)(g_styles + b * CIN + c);
        uint32_t lo = f2_to_e4m3x2(xv.x * sv.x, xv.y * sv.y);
        uint32_t hi = f2_to_e4m3x2(xv.z * sv.z, xv.w * sv.w);
        *(uint32_t*)(g_xb + ((size_t)(c >> 7) * MTOT + m) * 128 + (c & 127)) = lo | (hi << 16);
    }
}

// ---------------------------------------------------------------- GEMM (R12: split-N overlap)
__global__ void __launch_bounds__(192, 1)
k_gemm(const __grid_constant__ CUtensorMap tmA,
       const __grid_constant__ CUtensorMap tmB,
       const float* __restrict__ x, const float* __restrict__ bias,
       const float* __restrict__ ls, float* __restrict__ out) {
    extern __shared__ uint8_t dsm[];
    const int tid = threadIdx.x;
    const int wid = tid >> 5;
    const int lane = tid & 31;
    const int bn0 = blockIdx.x * GBN;
    const int bm0 = blockIdx.y * GBM;
    const int batch = bm0 >> 12;

#if USE_TCGEN05
    __shared__ __align__(8) uint64_t s_full[GSTAGES], s_empty[GSTAGES], s_done[2];
    __shared__ uint32_t s_tmem;
    __shared__ __align__(16) float s_bias[GBN], s_ls[GBN], s_dco[GBN];

    const uint32_t base = (smem_u32(dsm) + 1023u) & ~1023u;

    if (tid == 0) {
        #pragma unroll
        for (int s = 0; s < GSTAGES; s++) {
            MBARRIER_INIT(smem_u32(&s_full[s]), 1);
            MBARRIER_INIT(smem_u32(&s_empty[s]), 1);
        }
        MBARRIER_INIT(smem_u32(&s_done[0]), 1);
        MBARRIER_INIT(smem_u32(&s_done[1]), 1);
        asm volatile("fence.proxy.async.shared::cta;" ::: "memory");
    }
    if (wid == 0) TCGEN05_ALLOC(smem_u32(&s_tmem), 256);

    for (int n = tid; n < GBN; n += 192) {
        s_bias[n] = bias[bn0 + n];
        s_ls[n]   = ls[bn0 + n];
        s_dco[n]  = g_dcoefs[batch * COUT + bn0 + n];
    }
    __syncthreads();
    const uint32_t tmem = s_tmem;

    if (wid == 4) {
        // ---------------- TMA producer: 2 N-halves x 8 K-steps, 32KB stages ----------------
        if (elect_one_pred()) {
            int pph = 1;
            int s = 0;
            #pragma unroll
            for (int h = 0; h < 2; h++) {
                for (int kt = 0; kt < GNKT; kt++) {
                    MBARRIER_WAIT_PARITY(smem_u32(&s_empty[s]), pph);
                    const uint32_t stg = base + s * STAGE_BYTES;
                    const uint32_t fb = smem_u32(&s_full[s]);
                    MBARRIER_EXPECT_TX(fb, STAGE_BYTES);
                    TMA_LOAD_3D(stg,            &tmA, 0, bm0,            kt, fb);  // A (L2-hot on h=1)
                    TMA_LOAD_3D(stg + AH_STAGE, &tmB, 0, bn0 + h * GBNH, kt, fb);
                    if (++s == GSTAGES) { s = 0; pph ^= 1; }
                }
            }
        }
    } else if (wid == 5) {
        // ---------------- MMA issuer: half 0 -> done[0], half 1 -> done[1] ----------------
        if (elect_one_pred()) {
            int cph = 0;
            int s = 0;
            #pragma unroll
            for (int h = 0; h < 2; h++) {
                const uint32_t dst = tmem + h * 128;
                for (int kt = 0; kt < GNKT; kt++) {
                    MBARRIER_WAIT_PARITY(smem_u32(&s_full[s]), cph);
                    const uint32_t stg = base + s * STAGE_BYTES;
                    const uint64_t ad = MAKE_SMEM_DESC(stg);
                    const uint64_t bd = MAKE_SMEM_DESC(stg + AH_STAGE);
                    #pragma unroll
                    for (int j = 0; j < 4; j++) {   // K=32 e4m3 per MMA, +2 desc units per step
                        const uint32_t en = (kt | j) ? 1u : 0u;
                        mma_f8_ss(dst, ad + j * 2, bd + j * 2, IDESC_F8, en);
                    }
                    TCGEN05_COMMIT(smem_u32(&s_empty[s]));
                    if (++s == GSTAGES) { s = 0; cph ^= 1; }
                }
                TCGEN05_COMMIT(smem_u32(&s_done[h]));   // half h drains while half h+1 accumulates
            }
        }
    } else if (wid < 4) {
        // ---------------- epilogue warps 0..3: drains half 0 during half 1's mainloop ----------------
        const int gm = bm0 + wid * 32 + lane;
        const float* xr = x + (size_t)gm * COUT + bn0;
        float* orow = out + (size_t)gm * COUT + bn0;

        float4 xb0[8], xb1[8];
        #pragma unroll
        for (int q = 0; q < 8; q++) xb0[q] = *(const float4*)(xr + q * 4);
        #pragma unroll
        for (int q = 0; q < 8; q++) xb1[q] = *(const float4*)(xr + 32 + q * 4);

        uint32_t t0[32], t1[32];

        #pragma unroll
        for (int h = 0; h < 2; h++) {
            MBARRIER_WAIT_PARITY(smem_u32(&s_done[h]), 0);
            TCGEN05_FENCE_AFTER();
            TCGEN05_LD_32X32B_X32(t0, tmem + (h * 4) * 32);     // first chunk of half

            #pragma unroll
            for (int c4 = 0; c4 < 4; c4++) {
                const int ch = h * 4 + c4;
                uint32_t* tc = (ch & 1) ? t1 : t0;
                uint32_t* tn = (ch & 1) ? t0 : t1;
                float4*   xc = (ch & 1) ? xb1 : xb0;

                TCGEN05_WAIT_LD();
                if (c4 < 3)
                    TCGEN05_LD_32X32B_X32(tn, tmem + (ch + 1) * 32);

                const int nb = ch * 32;
                #pragma unroll
                for (int j = 0; j < 32; j += 4) {
                    const int n = nb + j;
                    const float4 bi = *(const float4*)(s_bias + n);
                    const float4 lv = *(const float4*)(s_ls + n);
                    const float4 dc = *(const float4*)(s_dco + n);
                    const float4 xv = xc[j >> 2];
                    float y0 = __uint_as_float(tc[j + 0]) * dc.x + bi.x;
                    float y1 = __uint_as_float(tc[j + 1]) * dc.y + bi.y;
                    float y2 = __uint_as_float(tc[j + 2]) * dc.z + bi.z;
                    float y3 = __uint_as_float(tc[j + 3]) * dc.w + bi.w;
                    y0 = (y0 > 0.f ? y0 : 0.2f * y0) * 1.4142135623730951f;
                    y1 = (y1 > 0.f ? y1 : 0.2f * y1) * 1.4142135623730951f;
                    y2 = (y2 > 0.f ? y2 : 0.2f * y2) * 1.4142135623730951f;
                    y3 = (y3 > 0.f ? y3 : 0.2f * y3) * 1.4142135623730951f;
                    y0 = fminf(fmaxf(y0, -256.f), 256.f);
                    y1 = fminf(fmaxf(y1, -256.f), 256.f);
                    y2 = fminf(fmaxf(y2, -256.f), 256.f);
                    y3 = fminf(fmaxf(y3, -256.f), 256.f);
                    float4 o;
                    o.x = y0 * lv.x + xv.x;
                    o.y = y1 * lv.y + xv.y;
                    o.z = y2 * lv.z + xv.z;
                    o.w = y3 * lv.w + xv.w;
                    *(float4*)(orow + n) = o;
                }
                if (ch < 6) {
                    const int n2 = (ch + 2) * 32;
                    #pragma unroll
                    for (int q = 0; q < 8; q++) xc[q] = *(const float4*)(xr + n2 + q * 4);
                }
            }
        }
    }

    __syncthreads();
    if (wid == 0) TCGEN05_DEALLOC(tmem, 256);

#else
    // ===== naive correctness fallback (plain-103 pass; never selected on GB300) =====
    for (int e = tid; e < GBM * GBN; e += 192) {
        const int mi = e / GBN, ni = e % GBN;
        const int gm = bm0 + mi, gn = bn0 + ni;
        float acc = 0.f;
        for (int kt = 0; kt < GNKT; kt++) {
            const uint8_t* ar = g_xb + ((size_t)kt * MTOT + gm) * 128;
            const uint8_t* br = g_wb + ((size_t)kt * COUT + gn) * 128;
            for (int kk = 0; kk < 128; kk++)
                acc += fp8_to_f(ar[kk]) * fp8_to_f(br[kk]);
        }
        float y = acc * g_dcoefs[batch * COUT + gn] + bias[gn];
        y = (y > 0.f ? y : 0.2f * y) * 1.4142135623730951f;
        y = fminf(fmaxf(y, -256.f), 256.f);
        out[(size_t)gm * COUT + gn] = y * ls[gn] + x[(size_t)gm * COUT + gn];
    }
#endif
}

// ---------------------------------------------------------------- launch
typedef CUresult (*EncodeTiledFn)(
    CUtensorMap*, CUtensorMapDataType, cuuint32_t, void*,
    const cuuint64_t*, const cuuint64_t*, const cuuint32_t*, const cuuint32_t*,
    CUtensorMapInterleave, CUtensorMapSwizzle, CUtensorMapL2promotion,
    CUtensorMapFloatOOBfill);

extern "C" void kernel_launch(void* const* d_in, const int* in_sizes, int n_in,
                              void* d_out, int out_size) {
    const float* x      = (const float*)d_in[0];
    const float* w      = (const float*)d_in[1];
    const float* weight = (const float*)d_in[2];
    const float* bias   = (const float*)d_in[3];
    const float* aff_w  = (const float*)d_in[4];
    const float* aff_b  = (const float*)d_in[5];
    const float* ls     = (const float*)d_in[6];
    float* out = (float*)d_out;

    k_styles<<<CIN, 256>>>(w, aff_w, aff_b);
    k_prep<<<COUT + (int)((size_t)MTOT * CIN / 4 / 256), 256>>>(weight, x);

    // tensormaps: 3D K-blocked fp8 — inner 128B, rows contiguous at 128B stride
    CUtensorMap tmA = {}, tmB = {};
    void* fn = nullptr;
    cudaDriverEntryPointQueryResult qr;
    cudaGetDriverEntryPointByVersion("cuTensorMapEncodeTiled", &fn, 12000,
                                     cudaEnableDefault, &qr);
    if (fn) {
        EncodeTiledFn encode = (EncodeTiledFn)fn;
        void *xb_ptr = nullptr, *wb_ptr = nullptr;
        cudaGetSymbolAddress(&xb_ptr, g_xb);
        cudaGetSymbolAddress(&wb_ptr, g_wb);
        {
            cuuint64_t dims[3] = {128, MTOT, GNKT};
            cuuint64_t str[2] = {128, (cuuint64_t)MTOT * 128};
            cuuint32_t box[3] = {128, GBM, 1};
            cuuint32_t es[3] = {1, 1, 1};
            encode(&tmA, CU_TENSOR_MAP_DATA_TYPE_UINT8, 3, xb_ptr, dims, str, box, es,
                   CU_TENSOR_MAP_INTERLEAVE_NONE, CU_TENSOR_MAP_SWIZZLE_128B,
                   CU_TENSOR_MAP_L2_PROMOTION_L2_128B, CU_TENSOR_MAP_FLOAT_OOB_FILL_NONE);
        }
        {
            cuuint64_t dims[3] = {128, COUT, GNKT};
            cuuint64_t str[2] = {128, (cuuint64_t)COUT * 128};
            cuuint32_t box[3] = {128, GBNH, 1};
            cuuint32_t es[3] = {1, 1, 1};
            encode(&tmB, CU_TENSOR_MAP_DATA_TYPE_UINT8, 3, wb_ptr, dims, str, box, es,
                   CU_TENSOR_MAP_INTERLEAVE_NONE, CU_TENSOR_MAP_SWIZZLE_128B,
                   CU_TENSOR_MAP_L2_PROMOTION_L2_128B, CU_TENSOR_MAP_FLOAT_OOB_FILL_NONE);
        }
    }

    cudaFuncSetAttribute(k_gemm, cudaFuncAttributeMaxDynamicSharedMemorySize, DYN_SMEM);
    dim3 grid(COUT / GBN, MTOT / GBM);
    k_gemm<<<grid, 192, DYN_SMEM>>>(tmA, tmB, x, bias, ls, out);
}